// round 10
// baseline (speedup 1.0000x reference)
#include <cuda_runtime.h>
#include <float.h>

#define BB 4
#define NR 180
#define CC 512
#define HH 48
#define WW 48
#define HW (HH*WW)
#define F_IN 2048
#define OO 64
#define EPSV 1e-5f
#define C4 (CC/4)          // 128 float4 per (h,w)
#define LVLSZ (BB*HH*WW*CC)
#define NTAB 6             // (pwh,pww): (1,1),(1,4),(4,1),(4,4),(12,1),(12,4)
#define CT 8               // channels per build block
#define SST 2305           // smem stride per channel in build
#define MT 12              // ROIs per gemm block
#define KS 16              // gemm k-split
#define KQ (F_IN/KS)       // 128

// ---------------- device scratch ----------------
__device__ float d_tab[NTAB * LVLSZ];           // 2D range-max tables, [p][C] layout
__device__ float d_pooled[BB * NR * F_IN];      // relu'd pooled
__device__ float d_W1t[F_IN * OO];              // W1 transposed [F,O]
__device__ float d_Wsum[OO];                    // sum_f W1[o,f]
__device__ float d_s1[NR];                      // per-n sum over (b,f)
__device__ float d_s2[NR];                      // per-n sumsq
__device__ float d_g16[KS][BB * NR * OO];       // GEMM k-slice partials

__device__ __forceinline__ void max4(float4& a, const float4& b) {
    a.x = fmaxf(a.x, b.x); a.y = fmaxf(a.y, b.y);
    a.z = fmaxf(a.z, b.z); a.w = fmaxf(a.w, b.w);
}

// ---------------- K1: fused transpose + 2D sparse-table build + W1 prep --------
// table index: tix = hsel*2 + wsel ; hsel: 0->pw1,1->pw4,2->pw12 ; wsel: 0->1,1->4
__global__ void __launch_bounds__(384) k_build(const float* __restrict__ feat,
                                               const float* __restrict__ W1) {
    int blk = blockIdx.x;
    int tid = threadIdx.x;

    if (blk >= (CC / CT) * BB) {
        // ---- W1 prep path ----
        int o = blk - (CC / CT) * BB;           // 0..63
        if (o == 0 && tid < NR) { d_s1[tid] = 0.f; d_s2[tid] = 0.f; }
        __shared__ float red[384];
        float s = 0.f;
        for (int f = tid; f < F_IN; f += 384) {
            float v = W1[o * F_IN + f];
            d_W1t[f * OO + o] = v;
            s += v;
        }
        red[tid] = s;
        __syncthreads();
        if (tid < 128) red[tid] += red[tid + 128] + red[tid + 256];  // 384 -> 128
        __syncthreads();
        for (int st = 64; st > 0; st >>= 1) {
            if (tid < st) red[tid] += red[tid + st];
            __syncthreads();
        }
        if (tid == 0) d_Wsum[o] = red[0];
        return;
    }

    // ---- build path ----
    extern __shared__ float ts[];            // CT*SST floats = 73.76KB
    int c0 = (blk & 63) * CT;
    int b = blk >> 6;

    const float4* src = (const float4*)(feat + ((size_t)(b * CC + c0)) * HW);
    int myc = tid / 48, myi = tid % 48;      // scan ownership
    float* colh = ts + myc * SST + myi;          // h-scan: column (c, w=myi), stride 48
    float* roww = ts + myc * SST + myi * 48;     // w-scan: row (c, h=myi), stride 1

    // ---- helpers as lambdas ----
    auto load_raw = [&]() {
        #pragma unroll
        for (int j = 0; j < (CT * HW) / (4 * 384); j++) {
            int i4 = tid + j * 384;
            float4 v = src[i4];
            int c = i4 / (HW / 4);
            int p = (i4 % (HW / 4)) * 4;
            float* d = ts + c * SST + p;
            d[0] = v.x; d[1] = v.y; d[2] = v.z; d[3] = v.w;
        }
    };
    auto write_tab = [&](int t) {
        float* dst = d_tab + (size_t)t * LVLSZ + (size_t)b * HW * CC + c0;
        #pragma unroll
        for (int j = 0; j < HW / 384; j++) {
            int p = tid + j * 384;
            float4 v0, v1;
            v0.x = ts[0 * SST + p]; v0.y = ts[1 * SST + p];
            v0.z = ts[2 * SST + p]; v0.w = ts[3 * SST + p];
            v1.x = ts[4 * SST + p]; v1.y = ts[5 * SST + p];
            v1.z = ts[6 * SST + p]; v1.w = ts[7 * SST + p];
            float4* dp = (float4*)(dst + (size_t)p * CC);
            dp[0] = v0; dp[1] = v1;
        }
    };
    auto hscan = [&](int d) {               // in-place ascending, thread owns column
        for (int h = 0; h < HH - d; h++)
            colh[h * 48] = fmaxf(colh[h * 48], colh[(h + d) * 48]);
    };
    auto wscan = [&](int d) {               // in-place ascending, thread owns row
        for (int w = 0; w < WW - d; w++)
            roww[w] = fmaxf(roww[w], roww[w + d]);
    };

    // chain A: raw -> (1,1) -> w:(1,4) -> h:(4,4) -> h:(12,4)
    load_raw();          __syncthreads();
    write_tab(0);        __syncthreads();   // (1,1)
    wscan(1); wscan(2);  __syncthreads();
    write_tab(1);        __syncthreads();   // (1,4)
    hscan(1); hscan(2);  __syncthreads();
    write_tab(3);        __syncthreads();   // (4,4)
    hscan(4); hscan(4);  __syncthreads();
    write_tab(5);        __syncthreads();   // (12,4)

    // chain B: raw -> h:(4,1) -> h:(12,1)
    load_raw();          __syncthreads();
    hscan(1); hscan(2);  __syncthreads();
    write_tab(2);        __syncthreads();   // (4,1)
    hscan(4); hscan(4);  __syncthreads();
    write_tab(4);                            // (12,1)
}

// ---------------- K2: ROI pool via 2D range-max lookups + ReLU + BN1 stats ------
__global__ void __launch_bounds__(256) k_roipool(const float* __restrict__ rois) {
    int bn = blockIdx.x;
    int b = bn / NR;
    const float* r = rois + bn * 4;
    int r0 = (int)truncf(r[0] * 0.25f), r1 = (int)truncf(r[1] * 0.25f);
    int r2 = (int)ceilf(r[2] * 0.25f),  r3 = (int)ceilf(r[3] * 0.25f);
    int hs = r2 - r0 + 1, ws = r3 - r1 + 1;
    int lenh = (hs + 1) >> 1;                 // both h-regions this length (1..24)
    int lenw = (ws + 1) >> 1;                 // both w-regions this length (1..12)
    int sh1 = r0 + (hs >> 1);
    int sw1 = r1 + (ws >> 1);

    int pwh, hsel;
    if (lenh >= 12)     { pwh = 12; hsel = 2; }
    else if (lenh >= 4) { pwh = 4;  hsel = 1; }
    else                { pwh = 1;  hsel = 0; }
    int pww = (lenw >= 4) ? 4 : 1;
    int wsel = (lenw >= 4) ? 1 : 0;
    int nh = (lenh + pwh - 1) / pwh;          // <= 3
    int nw = (lenw + pww - 1) / pww;          // <= 3
    const float4* L4 = (const float4*)(d_tab + (size_t)(hsel * 2 + wsel) * LVLSZ);

    int tid = threadIdx.x;
    int cq = tid & 127;
    int half = tid >> 7;
    int wstart = half ? sw1 : r1;
    size_t rb = (size_t)(b * HH) * WW;

    const float4 NEG = make_float4(-FLT_MAX, -FLT_MAX, -FLT_MAX, -FLT_MAX);
    float4 m0 = NEG, m1 = NEG;
    int capH = lenh - pwh, capW = lenw - pww;
    for (int jh = 0; jh < nh; jh++) {
        int ho = jh * pwh; if (ho > capH) ho = capH;
        const float4* rA = L4 + (rb + (size_t)(r0  + ho) * WW) * C4 + cq;
        const float4* rB = L4 + (rb + (size_t)(sh1 + ho) * WW) * C4 + cq;
        #pragma unroll 3
        for (int jw = 0; jw < nw; jw++) {
            int wo = jw * pww; if (wo > capW) wo = capW;
            int wi = wstart + wo;
            max4(m0, rA[(size_t)wi * C4]);
            max4(m1, rB[(size_t)wi * C4]);
        }
    }

    __shared__ float4 sm0[128], sm1[128];
    __shared__ float rs[128], rq[128];
    if (half == 1) { sm0[cq] = m0; sm1[cq] = m1; }
    __syncthreads();
    if (half == 0) {
        const float4 Z = make_float4(0.f, 0.f, 0.f, 0.f);
        float4 m00 = m0, m10 = m1, m01 = sm0[cq], m11 = sm1[cq];
        max4(m00, Z); max4(m01, Z); max4(m10, Z); max4(m11, Z);
        float4 o0 = make_float4(m00.x, m01.x, m10.x, m11.x);
        float4 o1 = make_float4(m00.y, m01.y, m10.y, m11.y);
        float4 o2 = make_float4(m00.z, m01.z, m10.z, m11.z);
        float4 o3 = make_float4(m00.w, m01.w, m10.w, m11.w);
        float4* out = (float4*)(d_pooled + (size_t)bn * F_IN + cq * 16);
        out[0] = o0; out[1] = o1; out[2] = o2; out[3] = o3;
        float s = (o0.x + o0.y + o0.z + o0.w) + (o1.x + o1.y + o1.z + o1.w)
                + (o2.x + o2.y + o2.z + o2.w) + (o3.x + o3.y + o3.z + o3.w);
        float q = o0.x*o0.x + o0.y*o0.y + o0.z*o0.z + o0.w*o0.w
                + o1.x*o1.x + o1.y*o1.y + o1.z*o1.z + o1.w*o1.w
                + o2.x*o2.x + o2.y*o2.y + o2.z*o2.z + o2.w*o2.w
                + o3.x*o3.x + o3.y*o3.y + o3.z*o3.z + o3.w*o3.w;
        rs[cq] = s; rq[cq] = q;
    }
    __syncthreads();
    for (int st = 64; st > 0; st >>= 1) {
        if (tid < st) { rs[tid] += rs[tid + st]; rq[tid] += rq[tid + st]; }
        __syncthreads();
    }
    if (tid == 0) {
        int n = bn % NR;
        atomicAdd(&d_s1[n], rs[0]);
        atomicAdd(&d_s2[n], rq[0]);
    }
}

// ---------------- K3: GEMM v5 — 12 ROIs x 16 k-slices, 960 blocks ----------------
__global__ void __launch_bounds__(256) k_gemm() {
    __shared__ float xs[MT][KQ];             // 6KB
    __shared__ float part[8][MT][OO];        // 24KB
    int mb = blockIdx.x;                     // 0..59
    int ks = blockIdx.y;                     // 0..15
    int b = mb / (NR / MT);
    int n0 = (mb % (NR / MT)) * MT;
    int tid = threadIdx.x;

    const float4* P4 = (const float4*)d_pooled;
    for (int i4 = tid; i4 < MT * (KQ / 4); i4 += 256) {
        int nl = i4 >> 5, k4 = i4 & 31;
        float4 v = P4[((size_t)(b * NR + n0 + nl)) * (F_IN / 4) + ks * (KQ / 4) + k4];
        *(float4*)&xs[nl][k4 * 4] = v;
    }
    __syncthreads();

    int o2 = (tid & 31) * 2;
    int q = tid >> 5;                        // 0..7, covers 16 k (uniform per warp)
    float acc[MT][2] = {};
    const float* Wp = d_W1t + (size_t)(ks * KQ + q * 16) * OO;
    #pragma unroll
    for (int k = 0; k < 16; k += 4) {
        float2 w0 = *(const float2*)&Wp[(k + 0) * OO + o2];
        float2 w1 = *(const float2*)&Wp[(k + 1) * OO + o2];
        float2 w2 = *(const float2*)&Wp[(k + 2) * OO + o2];
        float2 w3 = *(const float2*)&Wp[(k + 3) * OO + o2];
        #pragma unroll
        for (int nl = 0; nl < MT; nl++) {
            float4 x = *(const float4*)&xs[nl][q * 16 + k];
            acc[nl][0] = fmaf(x.x, w0.x, acc[nl][0]);
            acc[nl][1] = fmaf(x.x, w0.y, acc[nl][1]);
            acc[nl][0] = fmaf(x.y, w1.x, acc[nl][0]);
            acc[nl][1] = fmaf(x.y, w1.y, acc[nl][1]);
            acc[nl][0] = fmaf(x.z, w2.x, acc[nl][0]);
            acc[nl][1] = fmaf(x.z, w2.y, acc[nl][1]);
            acc[nl][0] = fmaf(x.w, w3.x, acc[nl][0]);
            acc[nl][1] = fmaf(x.w, w3.y, acc[nl][1]);
        }
    }
    #pragma unroll
    for (int nl = 0; nl < MT; nl++)
        *(float2*)&part[q][nl][o2] = make_float2(acc[nl][0], acc[nl][1]);
    __syncthreads();

    for (int i = tid; i < MT * OO; i += 256) {
        int nl = i >> 6, o = i & 63;
        float g = 0.f;
        #pragma unroll
        for (int qq = 0; qq < 8; qq++) g += part[qq][nl][o];
        d_g16[ks][((size_t)(b * NR + n0 + nl)) * OO + o] = g;
    }
}

// ---------------- K4: finalize BN1 affine + bias + BN2 + write ----------------
__global__ void k_final(const float* __restrict__ gamma1,
                        const float* __restrict__ beta1,
                        const float* __restrict__ bl1,
                        const float* __restrict__ gamma2,
                        const float* __restrict__ beta2,
                        float* __restrict__ out) {
    int n = blockIdx.x;
    int t = threadIdx.x;
    int b = t >> 6, o = t & 63;

    const float inv1 = 1.0f / (BB * F_IN);
    float mean1 = d_s1[n] * inv1;
    float var1 = d_s2[n] * inv1 - mean1 * mean1;
    float a1 = gamma1[n] * rsqrtf(var1 + EPSV);
    float c1 = beta1[n] - a1 * mean1;

    size_t gi = ((size_t)(b * NR + n)) * OO + o;
    float gsum = 0.f;
    #pragma unroll
    for (int ks = 0; ks < KS; ks++) gsum += d_g16[ks][gi];
    float y = a1 * gsum + c1 * d_Wsum[o] + bl1[o];

    __shared__ float rs[256], rq[256];
    rs[t] = y;
    rq[t] = y * y;
    __syncthreads();
    for (int st = 128; st > 0; st >>= 1) {
        if (t < st) { rs[t] += rs[t + st]; rq[t] += rq[t + st]; }
        __syncthreads();
    }
    float mean = rs[0] * (1.0f / 256.0f);
    float var = rq[0] * (1.0f / 256.0f) - mean * mean;
    out[gi] = (y - mean) * rsqrtf(var + EPSV) * gamma2[n] + beta2[n];
}

// ---------------- launch ----------------
extern "C" void kernel_launch(void* const* d_in, const int* in_sizes, int n_in,
                              void* d_out, int out_size) {
    const float* features = (const float*)d_in[0];
    const float* rois     = (const float*)d_in[1];
    const float* gamma1   = (const float*)d_in[2];
    const float* beta1    = (const float*)d_in[3];
    const float* W1       = (const float*)d_in[4];
    const float* bl1      = (const float*)d_in[5];
    const float* gamma2   = (const float*)d_in[6];
    const float* beta2    = (const float*)d_in[7];
    float* out = (float*)d_out;

    static bool attr_done = false;
    const int BUILD_SMEM = CT * SST * 4;     // 73760 B
    if (!attr_done) {
        cudaFuncSetAttribute(k_build, cudaFuncAttributeMaxDynamicSharedMemorySize, BUILD_SMEM);
        attr_done = true;
    }

    k_build<<<(CC / CT) * BB + OO, 384, BUILD_SMEM>>>(features, W1);
    k_roipool<<<BB * NR, 256>>>(rois);
    dim3 ggrid(BB * (NR / MT), KS);
    k_gemm<<<ggrid, 256>>>();
    k_final<<<NR, 256>>>(gamma1, beta1, bl1, gamma2, beta2, out);
}

// round 11
// speedup vs baseline: 1.9620x; 1.9620x over previous
#include <cuda_runtime.h>
#include <float.h>

#define BB 4
#define NR 180
#define CC 512
#define HH 48
#define WW 48
#define HW (HH*WW)
#define F_IN 2048
#define OO 64
#define EPSV 1e-5f
#define C4 (CC/4)          // 128 float4 per (h,w)
#define LVLSZ (BB*HH*WW*CC)
#define MT 12              // ROIs per gemm block
#define KS 16              // gemm k-split
#define KQ (F_IN/KS)       // 128
#define NBUILD (BB*WW*(CC/128))   // 768 column-scan blocks

// ---------------- device scratch ----------------
__device__ float d_feat_t[LVLSZ];               // [B,H,W,C] level pw=1 (transposed)
__device__ float d_lvl[2 * LVLSZ];              // levels pw=4, pw=12
__device__ float d_pooled[BB * NR * F_IN];      // relu'd pooled
__device__ float d_W1t[F_IN * OO];              // W1 transposed [F,O]
__device__ float d_Wsum[OO];                    // sum_f W1[o,f]
__device__ float d_s1[NR];                      // per-n sum over (b,f)
__device__ float d_s2[NR];                      // per-n sumsq
__device__ float d_g16[KS][BB * NR * OO];       // GEMM k-slice partials

__device__ __forceinline__ void max4(float4& a, const float4& b) {
    a.x = fmaxf(a.x, b.x); a.y = fmaxf(a.y, b.y);
    a.z = fmaxf(a.z, b.z); a.w = fmaxf(a.w, b.w);
}

// ---------------- K1: features [B,C,HW] -> [B,HW,C], tiled, coalesced ----------
__global__ void k_transpose(const float* __restrict__ feat) {
    __shared__ float tile[32][33];
    int b = blockIdx.z;
    int c0 = blockIdx.y * 32;
    int p0 = blockIdx.x * 32;       // HW=2304 divisible by 32
    #pragma unroll
    for (int k = 0; k < 32; k += 8) {
        int c = c0 + threadIdx.y + k;
        tile[threadIdx.y + k][threadIdx.x] =
            feat[((size_t)(b * CC + c)) * HW + p0 + threadIdx.x];
    }
    __syncthreads();
    #pragma unroll
    for (int k = 0; k < 32; k += 8) {
        int p = p0 + threadIdx.y + k;
        d_feat_t[((size_t)b * HW + p) * CC + c0 + threadIdx.x] =
            tile[threadIdx.x][threadIdx.y + k];
    }
}

// ---------------- K2: column-scan sparse-table build (coalesced) + W1 prep ------
// blocks 0..767: thread owns channel c of column (b,w); registers v[48].
// blocks 768..831: W1 transpose + row sums; block 768 also zeroes BN1 stats.
__global__ void __launch_bounds__(128) k_build4(const float* __restrict__ W1) {
    int blk = blockIdx.x;
    int tid = threadIdx.x;

    if (blk >= NBUILD) {
        int o = blk - NBUILD;                   // 0..63
        if (o == 0) {
            for (int i = tid; i < NR; i += 128) { d_s1[i] = 0.f; d_s2[i] = 0.f; }
        }
        __shared__ float red[128];
        float s = 0.f;
        for (int f = tid; f < F_IN; f += 128) {
            float v = W1[o * F_IN + f];
            d_W1t[f * OO + o] = v;
            s += v;
        }
        red[tid] = s;
        __syncthreads();
        for (int st = 64; st > 0; st >>= 1) {
            if (tid < st) red[tid] += red[tid + st];
            __syncthreads();
        }
        if (tid == 0) d_Wsum[o] = red[0];
        return;
    }

    int bw = blk >> 2;                  // (b,w)
    int cp = blk & 3;                   // channel part
    int b = bw / WW, w = bw % WW;
    int c = cp * 128 + tid;

    size_t base = ((size_t)(b * HH) * WW + w) * CC + c;
    const size_t HS = (size_t)WW * CC;  // h stride

    float v[HH];
    #pragma unroll
    for (int h = 0; h < HH; h++) v[h] = d_feat_t[base + h * HS];

    // pw1 -> pw4: passes d=1 then d=2
    #pragma unroll
    for (int h = 0; h < HH - 1; h++) v[h] = fmaxf(v[h], v[h + 1]);
    #pragma unroll
    for (int h = 0; h < HH - 2; h++) v[h] = fmaxf(v[h], v[h + 2]);
    #pragma unroll
    for (int h = 0; h < HH; h++) d_lvl[base + h * HS] = v[h];           // pw4

    // pw4 -> pw12: two d=4 passes
    #pragma unroll
    for (int h = 0; h < HH - 4; h++) v[h] = fmaxf(v[h], v[h + 4]);
    #pragma unroll
    for (int h = 0; h < HH - 8; h++) v[h] = fmaxf(v[h], v[h + 4]);
    #pragma unroll
    for (int h = 0; h < HH; h++) d_lvl[LVLSZ + base + h * HS] = v[h];   // pw12
}

// ---------------- K3: ROI pool via range-max lookups + ReLU + BN1 stats --------
__global__ void __launch_bounds__(256) k_roipool(const float* __restrict__ rois) {
    int bn = blockIdx.x;
    int b = bn / NR;
    const float* r = rois + bn * 4;
    int r0 = (int)truncf(r[0] * 0.25f), r1 = (int)truncf(r[1] * 0.25f);
    int r2 = (int)ceilf(r[2] * 0.25f),  r3 = (int)ceilf(r[3] * 0.25f);
    int hs = r2 - r0 + 1, ws = r3 - r1 + 1;
    int lenh = (hs + 1) >> 1;
    int lenw = (ws + 1) >> 1;
    int sh1 = r0 + (hs >> 1);
    int sw1 = r1 + (ws >> 1);

    const float* Lf;
    int pw;
    if (lenh >= 12)     { pw = 12; Lf = d_lvl + (size_t)LVLSZ; }
    else if (lenh >= 4) { pw = 4;  Lf = d_lvl; }
    else                { pw = 1;  Lf = d_feat_t; }
    int nlk = (lenh + pw - 1) / pw;       // 1..3
    const float4* L4 = (const float4*)Lf;

    int tid = threadIdx.x;
    int cq = tid & 127;
    int half = tid >> 7;
    int wstart = half ? sw1 : r1;
    size_t rb = (size_t)(b * HH) * WW;

    const float4 NEG = make_float4(-FLT_MAX, -FLT_MAX, -FLT_MAX, -FLT_MAX);
    float4 m0 = NEG, m1 = NEG;
    int cap = lenh - pw;
    for (int j = 0; j < nlk; j++) {
        int ho = j * pw; if (ho > cap) ho = cap;
        const float4* pA = L4 + (rb + (size_t)(r0  + ho) * WW + wstart) * C4 + cq;
        const float4* pB = L4 + (rb + (size_t)(sh1 + ho) * WW + wstart) * C4 + cq;
        #pragma unroll 2
        for (int w = lenw; w > 0; --w) {
            float4 va = *pA, vb = *pB;
            pA += C4; pB += C4;
            max4(m0, va); max4(m1, vb);
        }
    }

    __shared__ float4 sm0[128], sm1[128];
    __shared__ float rs[128], rq[128];
    if (half == 1) { sm0[cq] = m0; sm1[cq] = m1; }
    __syncthreads();
    if (half == 0) {
        const float4 Z = make_float4(0.f, 0.f, 0.f, 0.f);
        float4 m00 = m0, m10 = m1, m01 = sm0[cq], m11 = sm1[cq];
        max4(m00, Z); max4(m01, Z); max4(m10, Z); max4(m11, Z);
        float4 o0 = make_float4(m00.x, m01.x, m10.x, m11.x);
        float4 o1 = make_float4(m00.y, m01.y, m10.y, m11.y);
        float4 o2 = make_float4(m00.z, m01.z, m10.z, m11.z);
        float4 o3 = make_float4(m00.w, m01.w, m10.w, m11.w);
        float4* out = (float4*)(d_pooled + (size_t)bn * F_IN + cq * 16);
        out[0] = o0; out[1] = o1; out[2] = o2; out[3] = o3;
        float s = (o0.x + o0.y + o0.z + o0.w) + (o1.x + o1.y + o1.z + o1.w)
                + (o2.x + o2.y + o2.z + o2.w) + (o3.x + o3.y + o3.z + o3.w);
        float q = o0.x*o0.x + o0.y*o0.y + o0.z*o0.z + o0.w*o0.w
                + o1.x*o1.x + o1.y*o1.y + o1.z*o1.z + o1.w*o1.w
                + o2.x*o2.x + o2.y*o2.y + o2.z*o2.z + o2.w*o2.w
                + o3.x*o3.x + o3.y*o3.y + o3.z*o3.z + o3.w*o3.w;
        rs[cq] = s; rq[cq] = q;
    }
    __syncthreads();
    for (int st = 64; st > 0; st >>= 1) {
        if (tid < st) { rs[tid] += rs[tid + st]; rq[tid] += rq[tid + st]; }
        __syncthreads();
    }
    if (tid == 0) {
        int n = bn % NR;
        atomicAdd(&d_s1[n], rs[0]);
        atomicAdd(&d_s2[n], rq[0]);
    }
}

// ---------------- K4: GEMM v5 — 12 ROIs x 16 k-slices, 960 blocks ----------------
__global__ void __launch_bounds__(256) k_gemm() {
    __shared__ float xs[MT][KQ];             // 6KB
    __shared__ float part[8][MT][OO];        // 24KB
    int mb = blockIdx.x;                     // 0..59
    int ks = blockIdx.y;                     // 0..15
    int b = mb / (NR / MT);
    int n0 = (mb % (NR / MT)) * MT;
    int tid = threadIdx.x;

    const float4* P4 = (const float4*)d_pooled;
    for (int i4 = tid; i4 < MT * (KQ / 4); i4 += 256) {
        int nl = i4 >> 5, k4 = i4 & 31;
        float4 v = P4[((size_t)(b * NR + n0 + nl)) * (F_IN / 4) + ks * (KQ / 4) + k4];
        *(float4*)&xs[nl][k4 * 4] = v;
    }
    __syncthreads();

    int o2 = (tid & 31) * 2;
    int q = tid >> 5;                        // 0..7, covers 16 k (uniform per warp)
    float acc[MT][2] = {};
    const float* Wp = d_W1t + (size_t)(ks * KQ + q * 16) * OO;
    #pragma unroll
    for (int k = 0; k < 16; k += 4) {
        float2 w0 = *(const float2*)&Wp[(k + 0) * OO + o2];
        float2 w1 = *(const float2*)&Wp[(k + 1) * OO + o2];
        float2 w2 = *(const float2*)&Wp[(k + 2) * OO + o2];
        float2 w3 = *(const float2*)&Wp[(k + 3) * OO + o2];
        #pragma unroll
        for (int nl = 0; nl < MT; nl++) {
            float4 x = *(const float4*)&xs[nl][q * 16 + k];
            acc[nl][0] = fmaf(x.x, w0.x, acc[nl][0]);
            acc[nl][1] = fmaf(x.x, w0.y, acc[nl][1]);
            acc[nl][0] = fmaf(x.y, w1.x, acc[nl][0]);
            acc[nl][1] = fmaf(x.y, w1.y, acc[nl][1]);
            acc[nl][0] = fmaf(x.z, w2.x, acc[nl][0]);
            acc[nl][1] = fmaf(x.z, w2.y, acc[nl][1]);
            acc[nl][0] = fmaf(x.w, w3.x, acc[nl][0]);
            acc[nl][1] = fmaf(x.w, w3.y, acc[nl][1]);
        }
    }
    #pragma unroll
    for (int nl = 0; nl < MT; nl++)
        *(float2*)&part[q][nl][o2] = make_float2(acc[nl][0], acc[nl][1]);
    __syncthreads();

    for (int i = tid; i < MT * OO; i += 256) {
        int nl = i >> 6, o = i & 63;
        float g = 0.f;
        #pragma unroll
        for (int qq = 0; qq < 8; qq++) g += part[qq][nl][o];
        d_g16[ks][((size_t)(b * NR + n0 + nl)) * OO + o] = g;
    }
}

// ---------------- K5: finalize BN1 affine + bias + BN2 + write ----------------
__global__ void k_final(const float* __restrict__ gamma1,
                        const float* __restrict__ beta1,
                        const float* __restrict__ bl1,
                        const float* __restrict__ gamma2,
                        const float* __restrict__ beta2,
                        float* __restrict__ out) {
    int n = blockIdx.x;
    int t = threadIdx.x;
    int b = t >> 6, o = t & 63;

    const float inv1 = 1.0f / (BB * F_IN);
    float mean1 = d_s1[n] * inv1;
    float var1 = d_s2[n] * inv1 - mean1 * mean1;
    float a1 = gamma1[n] * rsqrtf(var1 + EPSV);
    float c1 = beta1[n] - a1 * mean1;

    size_t gi = ((size_t)(b * NR + n)) * OO + o;
    float gsum = 0.f;
    #pragma unroll
    for (int ks = 0; ks < KS; ks++) gsum += d_g16[ks][gi];
    float y = a1 * gsum + c1 * d_Wsum[o] + bl1[o];

    __shared__ float rs[256], rq[256];
    rs[t] = y;
    rq[t] = y * y;
    __syncthreads();
    for (int st = 128; st > 0; st >>= 1) {
        if (t < st) { rs[t] += rs[t + st]; rq[t] += rq[t + st]; }
        __syncthreads();
    }
    float mean = rs[0] * (1.0f / 256.0f);
    float var = rq[0] * (1.0f / 256.0f) - mean * mean;
    out[gi] = (y - mean) * rsqrtf(var + EPSV) * gamma2[n] + beta2[n];
}

// ---------------- launch ----------------
extern "C" void kernel_launch(void* const* d_in, const int* in_sizes, int n_in,
                              void* d_out, int out_size) {
    const float* features = (const float*)d_in[0];
    const float* rois     = (const float*)d_in[1];
    const float* gamma1   = (const float*)d_in[2];
    const float* beta1    = (const float*)d_in[3];
    const float* W1       = (const float*)d_in[4];
    const float* bl1      = (const float*)d_in[5];
    const float* gamma2   = (const float*)d_in[6];
    const float* beta2    = (const float*)d_in[7];
    float* out = (float*)d_out;

    dim3 tgrid(HW / 32, CC / 32, BB);
    k_transpose<<<tgrid, dim3(32, 8)>>>(features);
    k_build4<<<NBUILD + OO, 128>>>(W1);
    k_roipool<<<BB * NR, 256>>>(rois);
    dim3 ggrid(BB * (NR / MT), KS);
    k_gemm<<<ggrid, 256>>>();
    k_final<<<NR, 256>>>(gamma1, beta1, bl1, gamma2, beta2, out);
}